// round 1
// baseline (speedup 1.0000x reference)
#include <cuda_runtime.h>
#include <cstdint>
#include <math.h>

#define BB 64
#define SS 512
#define EE 256
#define HH 512
#define HD 1024
#define G4 2048              // 4*H
#define NG 4096              // 2 dirs * 4H
#define TT 9

// ---------------- static device buffers (no allocation allowed) ----------------
__device__ float d_x0[(size_t)BB * SS * EE];                 // embedded input
__device__ float d_xg0[(size_t)2 * SS * BB * G4];            // layer0 input proj, [d][t][b][gate]
__device__ float d_x1[(size_t)BB * SS * HD];                 // layer0 output / layer1 input
__device__ float d_xg1[(size_t)2 * SS * BB * G4];            // layer1 input proj
__device__ float d_x2[(size_t)BB * SS * HD];                 // layer1 output
__device__ float d_logits[(size_t)BB * SS * TT];
__device__ float d_hbuf[2 * 2 * HH * BB];                    // [dir][pingpong][k][m]
__device__ float d_llh[BB];
__device__ unsigned g_bar_cnt;                               // zero-init
__device__ unsigned g_bar_gen;                               // zero-init

// ---------------- grid barrier (all blocks co-resident) ----------------
__device__ __forceinline__ void grid_barrier(int nb) {
    __syncthreads();
    if (threadIdx.x == 0) {
        __threadfence();
        unsigned g = atomicAdd(&g_bar_gen, 0u);
        unsigned r = atomicAdd(&g_bar_cnt, 1u);
        if (r == (unsigned)nb - 1u) {
            atomicExch(&g_bar_cnt, 0u);
            __threadfence();
            atomicAdd(&g_bar_gen, 1u);
        } else {
            while (atomicAdd(&g_bar_gen, 0u) == g) { __nanosleep(128); }
        }
        __threadfence();
    }
    __syncthreads();
}

// ---------------- embedding gather ----------------
__global__ void k_embed(const int* __restrict__ ids, const float* __restrict__ emb) {
    int row = blockIdx.x;                                    // 0..B*S-1
    const float4* src = (const float4*)(emb + (size_t)ids[row] * EE);
    float4* dst = (float4*)(d_x0 + (size_t)row * EE);
    dst[threadIdx.x] = src[threadIdx.x];                     // 64 threads * float4 = 256
}

// ---------------- input-projection GEMM: xg[d][s][b][g] = A @ W^T + bias ----------------
// A: [32768][K] row-major (row m = b*512+s), W: [4096][K] row-major, K = 256 (ph0) / 1024 (ph1)
template <int PH>
__global__ void __launch_bounds__(256, 2) k_gemm_xg(const float* __restrict__ W,
                                                    const float* __restrict__ bih,
                                                    const float* __restrict__ bhh) {
    constexpr int K = (PH == 0) ? EE : HD;
    const float* A = (PH == 0) ? (const float*)d_x0 : (const float*)d_x1;
    float* xg      = (PH == 0) ? d_xg0 : d_xg1;

    __shared__ float As[16][132];
    __shared__ float Bs[16][132];

    const int m0 = blockIdx.y * 128;
    const int n0 = blockIdx.x * 128;
    const int tid = threadIdx.x;
    const int tm = tid >> 4;       // 0..15
    const int tn = tid & 15;       // 0..15

    float acc[8][8];
#pragma unroll
    for (int i = 0; i < 8; i++)
#pragma unroll
        for (int j = 0; j < 8; j++) acc[i][j] = 0.f;

    const int r = tid >> 1;
    const int cbase = (tid & 1) * 8;

    for (int k0 = 0; k0 < K; k0 += 16) {
        // load + transpose A tile (128 x 16)
        {
            const float* ap = A + (size_t)(m0 + r) * K + k0 + cbase;
            float4 v0 = *(const float4*)ap;
            float4 v1 = *(const float4*)(ap + 4);
            As[cbase + 0][r] = v0.x; As[cbase + 1][r] = v0.y;
            As[cbase + 2][r] = v0.z; As[cbase + 3][r] = v0.w;
            As[cbase + 4][r] = v1.x; As[cbase + 5][r] = v1.y;
            As[cbase + 6][r] = v1.z; As[cbase + 7][r] = v1.w;
            const float* bp = W + (size_t)(n0 + r) * K + k0 + cbase;
            float4 w0 = *(const float4*)bp;
            float4 w1 = *(const float4*)(bp + 4);
            Bs[cbase + 0][r] = w0.x; Bs[cbase + 1][r] = w0.y;
            Bs[cbase + 2][r] = w0.z; Bs[cbase + 3][r] = w0.w;
            Bs[cbase + 4][r] = w1.x; Bs[cbase + 5][r] = w1.y;
            Bs[cbase + 6][r] = w1.z; Bs[cbase + 7][r] = w1.w;
        }
        __syncthreads();
#pragma unroll
        for (int kk = 0; kk < 16; kk++) {
            float a[8], b[8];
            float4 a0 = *(const float4*)&As[kk][tm * 8];
            float4 a1 = *(const float4*)&As[kk][tm * 8 + 4];
            float4 b0 = *(const float4*)&Bs[kk][tn * 8];
            float4 b1 = *(const float4*)&Bs[kk][tn * 8 + 4];
            a[0]=a0.x;a[1]=a0.y;a[2]=a0.z;a[3]=a0.w;a[4]=a1.x;a[5]=a1.y;a[6]=a1.z;a[7]=a1.w;
            b[0]=b0.x;b[1]=b0.y;b[2]=b0.z;b[3]=b0.w;b[4]=b1.x;b[5]=b1.y;b[6]=b1.z;b[7]=b1.w;
#pragma unroll
            for (int i = 0; i < 8; i++)
#pragma unroll
                for (int j = 0; j < 8; j++) acc[i][j] += a[i] * b[j];
        }
        __syncthreads();
    }

    // epilogue: add bias, scatter to xg[d][s][b][gate]
#pragma unroll
    for (int j = 0; j < 8; j++) {
        int n = n0 + tn * 8 + j;
        float bias = bih[n] + bhh[n];
        int d = n >> 11;
        int gate = n & 2047;
#pragma unroll
        for (int i = 0; i < 8; i++) {
            int m = m0 + tm * 8 + i;
            int b = m >> 9;
            int s = m & 511;
            xg[((size_t)(d * SS + s) * BB + b) * G4 + gate] = acc[i][j] + bias;
        }
    }
}

// ---------------- persistent bidirectional LSTM scan ----------------
// 128 blocks: block = (dir, 8 hidden units). 128 threads/block.
// per step: G[64m][32c] = h[64][512] @ Wslice[512][32], c = g*8+jj (4 gate types x 8 units)
template <int PH>
__global__ void __launch_bounds__(128, 1) k_scan(const float* __restrict__ whh, int nb) {
    extern __shared__ float sm[];
    float* ws = sm;                       // [32][513]  weights, resident across all steps
    float* hs = sm + 32 * 513;            // [32][64]   h staging (k-major)
    float* Gs = hs + 32 * 64;             // [64][32]   gate pre-activations

    const float* xg = (PH == 0) ? d_xg0 : d_xg1;
    float* xout     = (PH == 0) ? d_x1  : d_x2;

    const int tid = threadIdx.x;
    const int d = blockIdx.x >> 6;        // direction
    const int jg = blockIdx.x & 63;
    const int j0 = jg * 8;                // hidden-unit base

    // preload recurrent weight slice: ws[c][k] = whh[d][g*512 + j0+jj][k]
    for (int idx = tid; idx < 32 * HH; idx += 128) {
        int c = idx >> 9;
        int k = idx & 511;
        int g = c >> 3, jj = c & 7;
        ws[c * 513 + k] = whh[((size_t)d * G4 + (size_t)g * HH + j0 + jj) * HH + k];
    }
    // zero h ping buffer rows owned by this block
    for (int idx = tid; idx < 8 * BB; idx += 128) {
        int jj = idx >> 6, m = idx & 63;
        d_hbuf[((d * 2 + 0) * HH + j0 + jj) * BB + m] = 0.f;
    }
    grid_barrier(nb);

    const int tm = tid >> 4;              // 0..7  (m group)
    const int tc = tid & 15;              // 0..15 (col pair)
    const int s0 = tid * 4;
    const int mm = s0 >> 3;               // batch index owned for gate phase
    const int jb = s0 & 7;                // 0 or 4

    float creg[4] = {0.f, 0.f, 0.f, 0.f};

    for (int t = 0; t < SS; t++) {
        const int tt = d ? (SS - 1 - t) : t;
        const float* hsrc = d_hbuf + ((size_t)(d * 2 + (t & 1)) * HH) * BB;

        float acc[8][2];
#pragma unroll
        for (int i = 0; i < 8; i++) { acc[i][0] = 0.f; acc[i][1] = 0.f; }

        for (int k0 = 0; k0 < HH; k0 += 32) {
            // stage 32x64 h chunk
            const float4* src4 = (const float4*)(hsrc + k0 * BB);
            float4* dst4 = (float4*)hs;
#pragma unroll
            for (int q = 0; q < 4; q++) dst4[tid + 128 * q] = src4[tid + 128 * q];
            __syncthreads();

            const float* wsb = ws + (2 * tc) * 513 + k0;
#pragma unroll
            for (int kk = 0; kk < 32; kk++) {
                float b0 = wsb[kk];
                float b1 = wsb[513 + kk];
                const float* ha = hs + kk * 64 + tm * 8;
                float4 a0 = *(const float4*)ha;
                float4 a1 = *(const float4*)(ha + 4);
                float a[8];
                a[0]=a0.x;a[1]=a0.y;a[2]=a0.z;a[3]=a0.w;a[4]=a1.x;a[5]=a1.y;a[6]=a1.z;a[7]=a1.w;
#pragma unroll
                for (int i = 0; i < 8; i++) {
                    acc[i][0] += a[i] * b0;
                    acc[i][1] += a[i] * b1;
                }
            }
            __syncthreads();
        }
        // publish gate sums
#pragma unroll
        for (int i = 0; i < 8; i++) {
            Gs[(tm * 8 + i) * 32 + 2 * tc]     = acc[i][0];
            Gs[(tm * 8 + i) * 32 + 2 * tc + 1] = acc[i][1];
        }
        __syncthreads();

        // gate phase: this thread owns states (mm, j0+jb .. j0+jb+3)
        const float* xgb = xg + (((size_t)d * SS + tt) * BB + mm) * G4 + j0 + jb;
        float4 gi = *(const float4*)(xgb + 0 * HH);
        float4 gf = *(const float4*)(xgb + 1 * HH);
        float4 gg = *(const float4*)(xgb + 2 * HH);
        float4 go = *(const float4*)(xgb + 3 * HH);
        float hnew[4];
        const float* gim = (const float*)&gi;
        const float* gfm = (const float*)&gf;
        const float* ggm = (const float*)&gg;
        const float* gom = (const float*)&go;
#pragma unroll
        for (int q = 0; q < 4; q++) {
            float vi = gim[q] + Gs[mm * 32 + 0 * 8 + jb + q];
            float vf = gfm[q] + Gs[mm * 32 + 1 * 8 + jb + q];
            float vg = ggm[q] + Gs[mm * 32 + 2 * 8 + jb + q];
            float vo = gom[q] + Gs[mm * 32 + 3 * 8 + jb + q];
            float si = 1.f / (1.f + expf(-vi));
            float sf = 1.f / (1.f + expf(-vf));
            float so = 1.f / (1.f + expf(-vo));
            float tg = tanhf(vg);
            creg[q] = sf * creg[q] + si * tg;
            hnew[q] = so * tanhf(creg[q]);
        }
        // write h into pong buffer + layer output
        float* hdst = d_hbuf + ((size_t)(d * 2 + ((t + 1) & 1)) * HH) * BB;
#pragma unroll
        for (int q = 0; q < 4; q++) hdst[(j0 + jb + q) * BB + mm] = hnew[q];
        float4 hv;
        hv.x = hnew[0]; hv.y = hnew[1]; hv.z = hnew[2]; hv.w = hnew[3];
        *(float4*)(xout + ((size_t)mm * SS + tt) * HD + d * HH + j0 + jb) = hv;

        grid_barrier(nb);
    }
}

// ---------------- classifier: logits = x2 @ cls_w^T + cls_b ----------------
__global__ void k_logits(const float* __restrict__ clsw, const float* __restrict__ clsb) {
    int gwarp = (blockIdx.x * blockDim.x + threadIdx.x) >> 5;
    int lane = threadIdx.x & 31;
    if (gwarp >= BB * SS) return;
    const float4* xr = (const float4*)(d_x2 + (size_t)gwarp * HD);
    float4 xv[8];
#pragma unroll
    for (int q = 0; q < 8; q++) xv[q] = xr[lane + 32 * q];
#pragma unroll
    for (int t = 0; t < TT; t++) {
        const float4* wr = (const float4*)(clsw + (size_t)t * HD);
        float p = 0.f;
#pragma unroll
        for (int q = 0; q < 8; q++) {
            float4 wv = wr[lane + 32 * q];
            p += xv[q].x * wv.x + xv[q].y * wv.y + xv[q].z * wv.z + xv[q].w * wv.w;
        }
#pragma unroll
        for (int o = 16; o > 0; o >>= 1) p += __shfl_down_sync(0xffffffffu, p, o);
        if (lane == 0) d_logits[(size_t)gwarp * TT + t] = p + clsb[t];
    }
}

// ---------------- CRF: fused Viterbi decode + log-partition + numerator ----------------
__global__ void k_crf(const int* __restrict__ labels, const int* __restrict__ vlens,
                      const float* __restrict__ trans, const float* __restrict__ startt,
                      const float* __restrict__ endt, float* __restrict__ out) {
    __shared__ float tr[TT * TT];
    __shared__ float alpha[TT], score[TT];
    __shared__ unsigned char hist[SS][TT];
    __shared__ float logZ_s;
    __shared__ int blast_s;

    const int b = blockIdx.x;
    const int tid = threadIdx.x;
    const int vl = vlens[b];
    const float* lg = d_logits + (size_t)b * SS * TT;
    const int* lab = labels + (size_t)b * SS;

    for (int i = tid; i < TT * TT; i += 32) tr[i] = trans[i];
    if (tid < TT) {
        float e = lg[tid];
        alpha[tid] = startt[tid] + e;
        score[tid] = startt[tid] + e;
    }
    __syncwarp();

    for (int t = 1; t < SS; t++) {
        float ns = 0.f, na = 0.f;
        int barg = 0;
        if (tid < TT) {
            float em = lg[t * TT + tid];
            float best = -1e30f, mx = -1e30f;
#pragma unroll
            for (int i = 0; i < TT; i++) {
                float v = score[i] + tr[i * TT + tid];
                if (v > best) { best = v; barg = i; }
                float a = alpha[i] + tr[i * TT + tid];
                mx = fmaxf(mx, a);
            }
            float ssum = 0.f;
#pragma unroll
            for (int i = 0; i < TT; i++) ssum += expf(alpha[i] + tr[i * TT + tid] - mx);
            ns = best + em;
            na = mx + logf(ssum) + em;
            hist[t][tid] = (unsigned char)barg;
        }
        __syncwarp();
        if (tid < TT && t < vl) { score[tid] = ns; alpha[tid] = na; }
        __syncwarp();
    }

    if (tid == 0) {
        float best = -1e30f, mx = -1e30f;
        int ba = 0;
        for (int j = 0; j < TT; j++) {
            float v = score[j] + endt[j];
            if (v > best) { best = v; ba = j; }
            mx = fmaxf(mx, alpha[j] + endt[j]);
        }
        float ss = 0.f;
        for (int j = 0; j < TT; j++) ss += expf(alpha[j] + endt[j] - mx);
        logZ_s = mx + logf(ss);
        blast_s = ba;
    }

    // numerator (parallel over t, warp reduce)
    float np = 0.f;
    for (int t = 1 + tid; t < SS; t += 32) {
        if (t < vl) np += lg[t * TT + lab[t]] + tr[lab[t - 1] * TT + lab[t]];
    }
#pragma unroll
    for (int o = 16; o > 0; o >>= 1) np += __shfl_down_sync(0xffffffffu, np, o);
    __syncwarp();

    if (tid == 0) {
        float num = startt[lab[0]] + lg[lab[0]] + np + endt[lab[vl - 1]];
        d_llh[b] = num - logZ_s;
        // backtrace
        int tag = blast_s;
        out[(size_t)b * SS + SS - 1] = (float)tag;
        for (int t = SS - 1; t >= 1; t--) {
            if (t < vl) tag = hist[t][tag];
            out[(size_t)b * SS + t - 1] = (float)tag;
        }
    }
}

__global__ void k_loss(float* __restrict__ out) {
    __shared__ float s[BB];
    s[threadIdx.x] = d_llh[threadIdx.x];
    __syncthreads();
    if (threadIdx.x == 0) {
        float t = 0.f;
        for (int i = 0; i < BB; i++) t += s[i];
        out[BB * SS] = -t / (float)BB;
    }
}

// ---------------- launch ----------------
extern "C" void kernel_launch(void* const* d_in, const int* in_sizes, int n_in,
                              void* d_out, int out_size) {
    const int*   ids    = (const int*)d_in[0];
    const int*   vlens  = (const int*)d_in[1];
    const int*   labels = (const int*)d_in[2];
    const float* emb    = (const float*)d_in[3];
    const float* w_ih0  = (const float*)d_in[4];
    const float* w_hh0  = (const float*)d_in[5];
    const float* b_ih0  = (const float*)d_in[6];
    const float* b_hh0  = (const float*)d_in[7];
    const float* w_ih1  = (const float*)d_in[8];
    const float* w_hh1  = (const float*)d_in[9];
    const float* b_ih1  = (const float*)d_in[10];
    const float* b_hh1  = (const float*)d_in[11];
    const float* cls_w  = (const float*)d_in[12];
    const float* cls_b  = (const float*)d_in[13];
    const float* trans  = (const float*)d_in[14];
    const float* start_t = (const float*)d_in[15];
    const float* end_t   = (const float*)d_in[16];
    float* out = (float*)d_out;

    const int SCAN_BLOCKS = 128;
    const int SCAN_SMEM = (32 * 513 + 32 * 64 + 64 * 32) * (int)sizeof(float);
    cudaFuncSetAttribute(k_scan<0>, cudaFuncAttributeMaxDynamicSharedMemorySize, SCAN_SMEM);
    cudaFuncSetAttribute(k_scan<1>, cudaFuncAttributeMaxDynamicSharedMemorySize, SCAN_SMEM);

    // 1. embedding
    k_embed<<<BB * SS, 64>>>(ids, emb);
    // 2. layer0 input projection
    {
        dim3 grid(NG / 128, (BB * SS) / 128);
        k_gemm_xg<0><<<grid, 256>>>(w_ih0, b_ih0, b_hh0);
    }
    // 3. layer0 recurrent scan
    k_scan<0><<<SCAN_BLOCKS, 128, SCAN_SMEM>>>(w_hh0, SCAN_BLOCKS);
    // 4. layer1 input projection
    {
        dim3 grid(NG / 128, (BB * SS) / 128);
        k_gemm_xg<1><<<grid, 256>>>(w_ih1, b_ih1, b_hh1);
    }
    // 5. layer1 recurrent scan
    k_scan<1><<<SCAN_BLOCKS, 128, SCAN_SMEM>>>(w_hh1, SCAN_BLOCKS);
    // 6. classifier
    k_logits<<<(BB * SS) / 8, 256>>>(cls_w, cls_b);
    // 7. CRF decode + loss pieces
    k_crf<<<BB, 32>>>(labels, vlens, trans, start_t, end_t, out);
    // 8. final loss
    k_loss<<<1, BB>>>(out);
}